// round 1
// baseline (speedup 1.0000x reference)
#include <cuda_runtime.h>

// Problem constants
#define NB     4
#define S_LEN  8192
#define E_DIM  1024
#define NHEAD  16
#define HD     64
#define M_TOT  (NB * S_LEN)   // 32768 token rows

// ---------------------------------------------------------------------------
// Scratch: Q, K, V projections and the scrambled attention output Y.
// __device__ globals are the sanctioned alloc-free scratch mechanism.
// ---------------------------------------------------------------------------
__device__ float g_Q[(size_t)M_TOT * E_DIM];
__device__ float g_K[(size_t)M_TOT * E_DIM];
__device__ float g_V[(size_t)M_TOT * E_DIM];
__device__ float g_Y[(size_t)M_TOT * E_DIM];

// ---------------------------------------------------------------------------
// SGEMM: C[M,N] = A[M,K] @ B[N,K]^T + bias[N]
// (nn.Linear convention: W stored [out_features, in_features] = [N, K])
// BM=BN=128, BK=16, 256 threads, 8x8 per-thread microtile, float4 everywhere.
// M, N, K are all multiples of the tile sizes here, so no bounds checks.
// ---------------------------------------------------------------------------
template <int BM, int BN, int BK, int TM, int TN>
__global__ __launch_bounds__(256)
void sgemm_bias_kernel(const float* __restrict__ A,
                       const float* __restrict__ B,
                       const float* __restrict__ bias,
                       float* __restrict__ C,
                       int M, int N, int K)
{
    __shared__ float As[BK][BM];
    __shared__ float Bs[BK][BN];

    const int tid  = threadIdx.x;
    const int cCol = blockIdx.x;   // N tile
    const int cRow = blockIdx.y;   // M tile

    const int tx = tid % (BN / TN);   // 0..15
    const int ty = tid / (BN / TN);   // 0..15

    const float* Ab = A + (size_t)cRow * BM * K;
    const float* Bb = B + (size_t)cCol * BN * K;

    // float4 staging along K
    const int lRow = tid / (BK / 4);        // 0..63
    const int lCol = (tid % (BK / 4)) * 4;  // 0,4,8,12
    const int rowStride = 256 / (BK / 4);   // 64

    float acc[TM][TN];
#pragma unroll
    for (int m = 0; m < TM; m++)
#pragma unroll
        for (int n = 0; n < TN; n++)
            acc[m][n] = 0.0f;

    for (int k0 = 0; k0 < K; k0 += BK) {
#pragma unroll
        for (int r = 0; r < BM; r += rowStride) {
            float4 t = *reinterpret_cast<const float4*>(
                Ab + (size_t)(lRow + r) * K + k0 + lCol);
            As[lCol + 0][lRow + r] = t.x;
            As[lCol + 1][lRow + r] = t.y;
            As[lCol + 2][lRow + r] = t.z;
            As[lCol + 3][lRow + r] = t.w;
        }
#pragma unroll
        for (int r = 0; r < BN; r += rowStride) {
            float4 t = *reinterpret_cast<const float4*>(
                Bb + (size_t)(lRow + r) * K + k0 + lCol);
            Bs[lCol + 0][lRow + r] = t.x;
            Bs[lCol + 1][lRow + r] = t.y;
            Bs[lCol + 2][lRow + r] = t.z;
            Bs[lCol + 3][lRow + r] = t.w;
        }
        __syncthreads();

#pragma unroll
        for (int kk = 0; kk < BK; kk++) {
            float regM[TM], regN[TN];
#pragma unroll
            for (int m = 0; m < TM; m++) regM[m] = As[kk][ty * TM + m];
#pragma unroll
            for (int n = 0; n < TN; n++) regN[n] = Bs[kk][tx * TN + n];
#pragma unroll
            for (int m = 0; m < TM; m++)
#pragma unroll
                for (int n = 0; n < TN; n++)
                    acc[m][n] += regM[m] * regN[n];
        }
        __syncthreads();
    }

    // epilogue: + bias, float4 stores
    float bb[TN];
#pragma unroll
    for (int n = 0; n < TN; n++)
        bb[n] = bias[cCol * BN + tx * TN + n];

    float* Cb = C + (size_t)(cRow * BM) * N + cCol * BN;
#pragma unroll
    for (int m = 0; m < TM; m++) {
#pragma unroll
        for (int n = 0; n < TN; n += 4) {
            float4 v;
            v.x = acc[m][n + 0] + bb[n + 0];
            v.y = acc[m][n + 1] + bb[n + 1];
            v.z = acc[m][n + 2] + bb[n + 2];
            v.w = acc[m][n + 3] + bb[n + 3];
            *reinterpret_cast<float4*>(Cb + (size_t)(ty * TM + m) * N + tx * TN + n) = v;
        }
    }
}

// ---------------------------------------------------------------------------
// Attention over the HEAD axis, per token (the faithful "buggy" einsum):
//   E[i][j] = (1/32) * dot64(Q_i(s), K_j(s))       (16x16 per token)
//   P = softmax_j(E)
//   O[i][d] = sum_j P[i][j] * V_j(s)[d]            (16x64 per token)
// The reshape scramble is fused into the store:
//   Y[n, i*512 + s/16, (s%16)*64 + d] = O[i][d]
//
// One warp per token. Lane l owns (i = l>>1, half = l&1):
//   energy:  j in [half*8, half*8+8)
//   output:  d in [half*32, half*32+32)
// ---------------------------------------------------------------------------
__global__ __launch_bounds__(128)
void attn_kernel(const float* __restrict__ Q,
                 const float* __restrict__ K,
                 const float* __restrict__ V,
                 float* __restrict__ Y)
{
    __shared__ float4 sQ[4][E_DIM / 4];
    __shared__ float4 sK[4][E_DIM / 4];
    __shared__ float4 sV[4][E_DIM / 4];

    const int w    = threadIdx.x >> 5;
    const int lane = threadIdx.x & 31;
    const int token = blockIdx.x * 4 + w;

    const size_t base4 = (size_t)token * (E_DIM / 4);
    const float4* Q4 = reinterpret_cast<const float4*>(Q) + base4;
    const float4* K4 = reinterpret_cast<const float4*>(K) + base4;
    const float4* V4 = reinterpret_cast<const float4*>(V) + base4;

#pragma unroll
    for (int c = 0; c < 8; c++) {
        sQ[w][lane + 32 * c] = Q4[lane + 32 * c];
        sK[w][lane + 32 * c] = K4[lane + 32 * c];
        sV[w][lane + 32 * c] = V4[lane + 32 * c];
    }
    __syncwarp();

    const int i    = lane >> 1;
    const int half = lane & 1;

    // --- energy for 8 j's ---
    float e[8];
#pragma unroll
    for (int jj = 0; jj < 8; jj++) {
        const int j = half * 8 + jj;
        float dot = 0.0f;
#pragma unroll
        for (int d4 = 0; d4 < 16; d4++) {
            float4 a = sQ[w][i * 16 + d4];
            float4 b = sK[w][j * 16 + d4];
            dot += a.x * b.x + a.y * b.y + a.z * b.z + a.w * b.w;
        }
        e[jj] = dot * 0.03125f;   // 1/sqrt(1024)
    }

    // --- softmax over all 16 j (pairwise exchange between lane 2i, 2i+1) ---
    float mx = e[0];
#pragma unroll
    for (int jj = 1; jj < 8; jj++) mx = fmaxf(mx, e[jj]);
    mx = fmaxf(mx, __shfl_xor_sync(0xffffffffu, mx, 1));

    float p[8], sum = 0.0f;
#pragma unroll
    for (int jj = 0; jj < 8; jj++) {
        p[jj] = __expf(e[jj] - mx);
        sum += p[jj];
    }
    sum += __shfl_xor_sync(0xffffffffu, sum, 1);
    const float inv = 1.0f / sum;

    float pj[16];
#pragma unroll
    for (int jj = 0; jj < 8; jj++) {
        float mine  = p[jj] * inv;
        float other = __shfl_xor_sync(0xffffffffu, mine, 1);
        pj[half * 8 + jj]       = mine;
        pj[(half ^ 1) * 8 + jj] = other;
    }

    // --- O[i][d] for d in [half*32, half*32+32), scatter-store with scramble ---
    const int n = token / S_LEN;
    const int s = token % S_LEN;
    float* Yrow = Y + ((size_t)(n * S_LEN + i * 512 + (s >> 4)) * E_DIM)
                    + ((s & 15) * 64) + half * 32;

#pragma unroll
    for (int d4 = 0; d4 < 8; d4++) {
        float4 acc = make_float4(0.f, 0.f, 0.f, 0.f);
#pragma unroll
        for (int j = 0; j < 16; j++) {
            float4 v = sV[w][j * 16 + half * 8 + d4];
            acc.x += pj[j] * v.x;
            acc.y += pj[j] * v.y;
            acc.z += pj[j] * v.z;
            acc.w += pj[j] * v.w;
        }
        *reinterpret_cast<float4*>(Yrow + d4 * 4) = acc;
    }
}

// ---------------------------------------------------------------------------
// Launch
// ---------------------------------------------------------------------------
extern "C" void kernel_launch(void* const* d_in, const int* in_sizes, int n_in,
                              void* d_out, int out_size)
{
    const float* x  = (const float*)d_in[0];
    const float* Wq = (const float*)d_in[1];
    const float* Wk = (const float*)d_in[2];
    const float* Wv = (const float*)d_in[3];
    const float* Wo = (const float*)d_in[4];
    const float* bq = (const float*)d_in[5];
    const float* bk = (const float*)d_in[6];
    const float* bv = (const float*)d_in[7];
    const float* bo = (const float*)d_in[8];
    float* out = (float*)d_out;

    float *Q, *K, *V, *Y;
    cudaGetSymbolAddress((void**)&Q, g_Q);
    cudaGetSymbolAddress((void**)&K, g_K);
    cudaGetSymbolAddress((void**)&V, g_V);
    cudaGetSymbolAddress((void**)&Y, g_Y);

    dim3 gblock(256);
    dim3 ggrid(E_DIM / 128, M_TOT / 128);

    sgemm_bias_kernel<128, 128, 16, 8, 8><<<ggrid, gblock>>>(x, Wq, bq, Q, M_TOT, E_DIM, E_DIM);
    sgemm_bias_kernel<128, 128, 16, 8, 8><<<ggrid, gblock>>>(x, Wk, bk, K, M_TOT, E_DIM, E_DIM);
    sgemm_bias_kernel<128, 128, 16, 8, 8><<<ggrid, gblock>>>(x, Wv, bv, V, M_TOT, E_DIM, E_DIM);

    attn_kernel<<<M_TOT / 4, 128>>>(Q, K, V, Y);

    sgemm_bias_kernel<128, 128, 16, 8, 8><<<ggrid, gblock>>>(Y, Wo, bo, out, M_TOT, E_DIM, E_DIM);
}

// round 2
// speedup vs baseline: 3.3329x; 3.3329x over previous
#include <cuda_runtime.h>
#include <cstdint>

// Problem constants
#define NB     4
#define S_LEN  8192
#define E_DIM  1024
#define NHEAD  16
#define HD     64
#define M_TOT  (NB * S_LEN)   // 32768 token rows

// GEMM tiling
#define BM 128
#define BN 128
#define BK 32
#define LDA 36                  // BK + 4 pad (16B-aligned stride, conflict-free frags)
#define STAGE_FLOATS (2 * BM * LDA)       // As + Bs for one stage
#define SMEM_BYTES  (2 * STAGE_FLOATS * 4) // double buffered: 73728 B

// ---------------------------------------------------------------------------
// Scratch
// ---------------------------------------------------------------------------
__device__ float g_Q[(size_t)M_TOT * E_DIM];
__device__ float g_K[(size_t)M_TOT * E_DIM];
__device__ float g_V[(size_t)M_TOT * E_DIM];
__device__ float g_Y[(size_t)M_TOT * E_DIM];

// ---------------------------------------------------------------------------
// Helpers
// ---------------------------------------------------------------------------
__device__ __forceinline__ void cp16(float* dst_smem, const float* src_gmem) {
    uint32_t d = (uint32_t)__cvta_generic_to_shared(dst_smem);
    asm volatile("cp.async.cg.shared.global [%0], [%1], 16;\n" :: "r"(d), "l"(src_gmem));
}
__device__ __forceinline__ uint32_t f2tf32(float f) {
    uint32_t u;
    asm("cvt.rna.tf32.f32 %0, %1;" : "=r"(u) : "f"(f));
    return u;
}
__device__ __forceinline__ void mma_tf32(float c[4],
                                         uint32_t a0, uint32_t a1, uint32_t a2, uint32_t a3,
                                         uint32_t b0, uint32_t b1) {
    asm volatile(
        "mma.sync.aligned.m16n8k8.row.col.f32.tf32.tf32.f32 "
        "{%0,%1,%2,%3}, {%4,%5,%6,%7}, {%8,%9}, {%0,%1,%2,%3};\n"
        : "+f"(c[0]), "+f"(c[1]), "+f"(c[2]), "+f"(c[3])
        : "r"(a0), "r"(a1), "r"(a2), "r"(a3), "r"(b0), "r"(b1));
}

// ---------------------------------------------------------------------------
// Tensor-core tf32 GEMM: C[M,N] = A[M,K] @ B[N,K]^T + bias[N]
// 256 threads = 8 warps (4 x 2), warp tile 32x64, block tile 128x128, BK=32.
// All dims are multiples of the tiles (M=32768, N=K=1024).
// ---------------------------------------------------------------------------
__global__ __launch_bounds__(256)
void tc_gemm_bias_kernel(const float* __restrict__ A,
                         const float* __restrict__ B,
                         const float* __restrict__ bias,
                         float* __restrict__ C,
                         int M, int N, int K)
{
    extern __shared__ float smem[];

    const int tid    = threadIdx.x;
    const int lane   = tid & 31;
    const int warpId = tid >> 5;
    const int warp_m = warpId & 3;   // 0..3  -> 32-row slab
    const int warp_n = warpId >> 2;  // 0..1  -> 64-col slab

    const int blockN = blockIdx.x * BN;
    const int blockM = blockIdx.y * BM;

    const float* Ab = A + (size_t)blockM * K;
    const float* Bb = B + (size_t)blockN * K;

    // staging indices: 1024 float4 per tile, 256 threads -> 4 each
    const int ldRow = tid >> 3;          // 0..31 base row
    const int ldC   = (tid & 7) * 4;     // float4 col within BK

    float acc[2][8][4];
#pragma unroll
    for (int mt = 0; mt < 2; mt++)
#pragma unroll
        for (int nt = 0; nt < 8; nt++)
#pragma unroll
            for (int c = 0; c < 4; c++)
                acc[mt][nt][c] = 0.0f;

    const int nIters = K / BK;

    // ---- prologue: load stage 0 ----
    {
        float* As = smem;
        float* Bs = smem + BM * LDA;
#pragma unroll
        for (int i = 0; i < 4; i++) {
            int row = ldRow + i * 32;
            cp16(As + row * LDA + ldC, Ab + (size_t)row * K + ldC);
            cp16(Bs + row * LDA + ldC, Bb + (size_t)row * K + ldC);
        }
        asm volatile("cp.async.commit_group;\n");
    }

    const int fragRow = lane >> 2;   // 0..7
    const int fragK   = lane & 3;    // 0..3

    for (int it = 0; it < nIters; it++) {
        // ---- issue next stage ----
        if (it + 1 < nIters) {
            const int k0 = (it + 1) * BK;
            float* As = smem + ((it + 1) & 1) * STAGE_FLOATS;
            float* Bs = As + BM * LDA;
#pragma unroll
            for (int i = 0; i < 4; i++) {
                int row = ldRow + i * 32;
                cp16(As + row * LDA + ldC, Ab + (size_t)row * K + k0 + ldC);
                cp16(Bs + row * LDA + ldC, Bb + (size_t)row * K + k0 + ldC);
            }
            asm volatile("cp.async.commit_group;\n");
            asm volatile("cp.async.wait_group 1;\n");
        } else {
            asm volatile("cp.async.wait_group 0;\n");
        }
        __syncthreads();

        const float* As = smem + (it & 1) * STAGE_FLOATS;
        const float* Bs = As + BM * LDA;

#pragma unroll
        for (int ks = 0; ks < BK / 8; ks++) {
            const int kb = ks * 8 + fragK;

            uint32_t af[2][4];
#pragma unroll
            for (int mt = 0; mt < 2; mt++) {
                const float* ap = As + (warp_m * 32 + mt * 16 + fragRow) * LDA + kb;
                af[mt][0] = f2tf32(ap[0]);
                af[mt][1] = f2tf32(ap[8 * LDA]);
                af[mt][2] = f2tf32(ap[4]);
                af[mt][3] = f2tf32(ap[8 * LDA + 4]);
            }
            uint32_t bf[8][2];
#pragma unroll
            for (int nt = 0; nt < 8; nt++) {
                const float* bp = Bs + (warp_n * 64 + nt * 8 + fragRow) * LDA + kb;
                bf[nt][0] = f2tf32(bp[0]);
                bf[nt][1] = f2tf32(bp[4]);
            }
#pragma unroll
            for (int mt = 0; mt < 2; mt++)
#pragma unroll
                for (int nt = 0; nt < 8; nt++)
                    mma_tf32(acc[mt][nt], af[mt][0], af[mt][1], af[mt][2], af[mt][3],
                             bf[nt][0], bf[nt][1]);
        }
        __syncthreads();
    }

    // ---- epilogue: bias + store ----
    const int colBase = blockN + warp_n * 64 + (lane & 3) * 2;
    const int rowBase = blockM + warp_m * 32 + (lane >> 2);
#pragma unroll
    for (int nt = 0; nt < 8; nt++) {
        const int col = colBase + nt * 8;
        const float b0 = bias[col], b1 = bias[col + 1];
#pragma unroll
        for (int mt = 0; mt < 2; mt++) {
            float* p0 = C + (size_t)(rowBase + mt * 16) * N + col;
            float* p1 = C + (size_t)(rowBase + mt * 16 + 8) * N + col;
            float2 v0 = make_float2(acc[mt][nt][0] + b0, acc[mt][nt][1] + b1);
            float2 v1 = make_float2(acc[mt][nt][2] + b0, acc[mt][nt][3] + b1);
            *reinterpret_cast<float2*>(p0) = v0;
            *reinterpret_cast<float2*>(p1) = v1;
        }
    }
}

// ---------------------------------------------------------------------------
// Attention over the HEAD axis, per token (faithful "buggy" einsum), with the
// (N,H,S,D)->(N,S,E) reshape scramble fused into the store. One warp/token.
// ---------------------------------------------------------------------------
__global__ __launch_bounds__(128)
void attn_kernel(const float* __restrict__ Q,
                 const float* __restrict__ K,
                 const float* __restrict__ V,
                 float* __restrict__ Y)
{
    __shared__ float4 sQ[4][E_DIM / 4];
    __shared__ float4 sK[4][E_DIM / 4];
    __shared__ float4 sV[4][E_DIM / 4];

    const int w    = threadIdx.x >> 5;
    const int lane = threadIdx.x & 31;
    const int token = blockIdx.x * 4 + w;

    const size_t base4 = (size_t)token * (E_DIM / 4);
    const float4* Q4 = reinterpret_cast<const float4*>(Q) + base4;
    const float4* K4 = reinterpret_cast<const float4*>(K) + base4;
    const float4* V4 = reinterpret_cast<const float4*>(V) + base4;

#pragma unroll
    for (int c = 0; c < 8; c++) {
        sQ[w][lane + 32 * c] = Q4[lane + 32 * c];
        sK[w][lane + 32 * c] = K4[lane + 32 * c];
        sV[w][lane + 32 * c] = V4[lane + 32 * c];
    }
    __syncwarp();

    const int i    = lane >> 1;
    const int half = lane & 1;

    float e[8];
#pragma unroll
    for (int jj = 0; jj < 8; jj++) {
        const int j = half * 8 + jj;
        float dot = 0.0f;
#pragma unroll
        for (int d4 = 0; d4 < 16; d4++) {
            float4 a = sQ[w][i * 16 + d4];
            float4 b = sK[w][j * 16 + d4];
            dot += a.x * b.x + a.y * b.y + a.z * b.z + a.w * b.w;
        }
        e[jj] = dot * 0.03125f;
    }

    float mx = e[0];
#pragma unroll
    for (int jj = 1; jj < 8; jj++) mx = fmaxf(mx, e[jj]);
    mx = fmaxf(mx, __shfl_xor_sync(0xffffffffu, mx, 1));

    float p[8], sum = 0.0f;
#pragma unroll
    for (int jj = 0; jj < 8; jj++) {
        p[jj] = __expf(e[jj] - mx);
        sum += p[jj];
    }
    sum += __shfl_xor_sync(0xffffffffu, sum, 1);
    const float inv = 1.0f / sum;

    float pj[16];
#pragma unroll
    for (int jj = 0; jj < 8; jj++) {
        float mine  = p[jj] * inv;
        float other = __shfl_xor_sync(0xffffffffu, mine, 1);
        pj[half * 8 + jj]       = mine;
        pj[(half ^ 1) * 8 + jj] = other;
    }

    const int n = token / S_LEN;
    const int s = token % S_LEN;
    float* Yrow = Y + ((size_t)(n * S_LEN + i * 512 + (s >> 4)) * E_DIM)
                    + ((s & 15) * 64) + half * 32;

#pragma unroll
    for (int d4 = 0; d4 < 8; d4++) {
        float4 acc = make_float4(0.f, 0.f, 0.f, 0.f);
#pragma unroll
        for (int j = 0; j < 16; j++) {
            float4 v = sV[w][j * 16 + half * 8 + d4];
            acc.x += pj[j] * v.x;
            acc.y += pj[j] * v.y;
            acc.z += pj[j] * v.z;
            acc.w += pj[j] * v.w;
        }
        *reinterpret_cast<float4*>(Yrow + d4 * 4) = acc;
    }
}

// ---------------------------------------------------------------------------
// Launch
// ---------------------------------------------------------------------------
extern "C" void kernel_launch(void* const* d_in, const int* in_sizes, int n_in,
                              void* d_out, int out_size)
{
    const float* x  = (const float*)d_in[0];
    const float* Wq = (const float*)d_in[1];
    const float* Wk = (const float*)d_in[2];
    const float* Wv = (const float*)d_in[3];
    const float* Wo = (const float*)d_in[4];
    const float* bq = (const float*)d_in[5];
    const float* bk = (const float*)d_in[6];
    const float* bv = (const float*)d_in[7];
    const float* bo = (const float*)d_in[8];
    float* out = (float*)d_out;

    float *Q, *K, *V, *Y;
    cudaGetSymbolAddress((void**)&Q, g_Q);
    cudaGetSymbolAddress((void**)&K, g_K);
    cudaGetSymbolAddress((void**)&V, g_V);
    cudaGetSymbolAddress((void**)&Y, g_Y);

    static bool attr_set = false;
    if (!attr_set) {
        cudaFuncSetAttribute(tc_gemm_bias_kernel,
                             cudaFuncAttributeMaxDynamicSharedMemorySize, SMEM_BYTES);
        attr_set = true;
    }

    dim3 gblock(256);
    dim3 ggrid(E_DIM / BN, M_TOT / BM);

    tc_gemm_bias_kernel<<<ggrid, gblock, SMEM_BYTES>>>(x, Wq, bq, Q, M_TOT, E_DIM, E_DIM);
    tc_gemm_bias_kernel<<<ggrid, gblock, SMEM_BYTES>>>(x, Wk, bk, K, M_TOT, E_DIM, E_DIM);
    tc_gemm_bias_kernel<<<ggrid, gblock, SMEM_BYTES>>>(x, Wv, bv, V, M_TOT, E_DIM, E_DIM);

    attn_kernel<<<M_TOT / 4, 128>>>(Q, K, V, Y);

    tc_gemm_bias_kernel<<<ggrid, gblock, SMEM_BYTES>>>(Y, Wo, bo, out, M_TOT, E_DIM, E_DIM);
}

// round 4
// speedup vs baseline: 4.5026x; 1.3509x over previous
#include <cuda_runtime.h>
#include <cuda_fp16.h>
#include <cstdint>

// ---------------------------------------------------------------------------
// Problem constants
// ---------------------------------------------------------------------------
#define NB     4
#define S_LEN  8192
#define E_DIM  1024
#define M_TOT  (NB * S_LEN)   // 32768

// ---------------------------------------------------------------------------
// GEMM tiling (fp16 mma.sync m16n8k16)
// ---------------------------------------------------------------------------
#define BM 128
#define BN 128
#define BKH 64                    // K-depth per stage, in halves (128 B rows)
#define LDH 72                    // padded smem row stride (halves) -> conflict-free
#define TILE_H   (BM * LDH)       // halves per (A or B) tile
#define STG_H    (2 * TILE_H)     // A + B per stage
#define SMEM_BYTES (2 * STG_H * 2)   // double buffer: 73728 B -> 2 CTAs/SM
#define NSTG (E_DIM / BKH)        // 16 k-stages

// ---------------------------------------------------------------------------
// Scratch (device globals = sanctioned alloc-free scratch)
// ---------------------------------------------------------------------------
__device__ __half g_Xh[(size_t)M_TOT * E_DIM];
__device__ __half g_Wh[4][(size_t)E_DIM * E_DIM];
__device__ __half g_Yh[(size_t)M_TOT * E_DIM];
__device__ float  g_Q[(size_t)M_TOT * E_DIM];
__device__ float  g_K[(size_t)M_TOT * E_DIM];
__device__ float  g_V[(size_t)M_TOT * E_DIM];

// ---------------------------------------------------------------------------
// Helpers
// ---------------------------------------------------------------------------
__device__ __forceinline__ void cp16(void* dst_smem, const void* src_gmem) {
    uint32_t d = (uint32_t)__cvta_generic_to_shared(dst_smem);
    asm volatile("cp.async.cg.shared.global [%0], [%1], 16;\n" :: "r"(d), "l"(src_gmem));
}
__device__ __forceinline__ void mma_f16(float c[4],
                                        uint32_t a0, uint32_t a1, uint32_t a2, uint32_t a3,
                                        uint32_t b0, uint32_t b1) {
    asm volatile(
        "mma.sync.aligned.m16n8k16.row.col.f32.f16.f16.f32 "
        "{%0,%1,%2,%3}, {%4,%5,%6,%7}, {%8,%9}, {%0,%1,%2,%3};\n"
        : "+f"(c[0]), "+f"(c[1]), "+f"(c[2]), "+f"(c[3])
        : "r"(a0), "r"(a1), "r"(a2), "r"(a3), "r"(b0), "r"(b1));
}

// ---------------------------------------------------------------------------
// fp16 tensor-core GEMM: C[M,N] = A[M,K] @ B[N,K]^T + bias[N]
// A, B fp16; accumulate fp32; C fp32.
// 256 threads = 8 warps (warp_m in {0,1} x warp_n in {0..3}), warp tile 64x32.
// ---------------------------------------------------------------------------
__global__ __launch_bounds__(256, 2)
void hgemm_bias_kernel(const __half* __restrict__ A,
                       const __half* __restrict__ B,
                       const float* __restrict__ bias,
                       float* __restrict__ C,
                       int M, int N, int K)
{
    extern __shared__ __align__(128) __half smem[];

    const int tid    = threadIdx.x;
    const int lane   = tid & 31;
    const int warpId = tid >> 5;
    const int warp_m = warpId & 1;    // 64-row slab
    const int warp_n = warpId >> 1;   // 32-col slab

    const int blockN = blockIdx.x * BN;
    const int blockM = blockIdx.y * BM;

    const __half* Ab = A + (size_t)blockM * K;
    const __half* Bb = B + (size_t)blockN * K;

    // staging: each tile = 128 rows x 8 chunks(16B); 1024 chunks; 4/thread/tile
    const int sRow = tid >> 1;              // 0..127
    const int sC   = (tid & 1) * 4;         // chunk 0..3 / 4..7  (pairs)

    float acc[4][4][4];
#pragma unroll
    for (int mt = 0; mt < 4; mt++)
#pragma unroll
        for (int nt = 0; nt < 4; nt++)
#pragma unroll
            for (int c = 0; c < 4; c++)
                acc[mt][nt][c] = 0.0f;

    auto load_stage = [&](int st) {
        const int k0 = st * BKH;
        __half* As = smem + (st & 1) * STG_H;
        __half* Bs = As + TILE_H;
#pragma unroll
        for (int c = 0; c < 4; c++) {
            cp16(As + sRow * LDH + (sC + c) * 8, Ab + (size_t)sRow * K + k0 + (sC + c) * 8);
            cp16(Bs + sRow * LDH + (sC + c) * 8, Bb + (size_t)sRow * K + k0 + (sC + c) * 8);
        }
        asm volatile("cp.async.commit_group;\n");
    };

    load_stage(0);
    load_stage(1);

    const int fr = lane >> 2;          // 0..7
    const int fk = (lane & 3) * 2;     // 0,2,4,6

    for (int it = 0; it < NSTG; it++) {
        if (it + 2 < NSTG) asm volatile("cp.async.wait_group 1;\n");
        else               asm volatile("cp.async.wait_group 0;\n");
        __syncthreads();

        const __half* As = smem + (it & 1) * STG_H;
        const __half* Bs = As + TILE_H;

#pragma unroll
        for (int ks = 0; ks < BKH / 16; ks++) {
            const int kb = ks * 16 + fk;

            uint32_t af[4][4];
#pragma unroll
            for (int mt = 0; mt < 4; mt++) {
                const __half* ap = As + (warp_m * 64 + mt * 16 + fr) * LDH + kb;
                af[mt][0] = *reinterpret_cast<const uint32_t*>(ap);
                af[mt][1] = *reinterpret_cast<const uint32_t*>(ap + 8 * LDH);
                af[mt][2] = *reinterpret_cast<const uint32_t*>(ap + 8);
                af[mt][3] = *reinterpret_cast<const uint32_t*>(ap + 8 * LDH + 8);
            }
            uint32_t bf[4][2];
#pragma unroll
            for (int nt = 0; nt < 4; nt++) {
                const __half* bp = Bs + (warp_n * 32 + nt * 8 + fr) * LDH + kb;
                bf[nt][0] = *reinterpret_cast<const uint32_t*>(bp);
                bf[nt][1] = *reinterpret_cast<const uint32_t*>(bp + 8);
            }
#pragma unroll
            for (int mt = 0; mt < 4; mt++)
#pragma unroll
                for (int nt = 0; nt < 4; nt++)
                    mma_f16(acc[mt][nt], af[mt][0], af[mt][1], af[mt][2], af[mt][3],
                            bf[nt][0], bf[nt][1]);
        }
        __syncthreads();

        if (it + 2 < NSTG) load_stage(it + 2);
    }

    // ---- epilogue: bias + fp32 store (float2) ----
    const int colBase = blockN + warp_n * 32 + (lane & 3) * 2;
    const int rowBase = blockM + warp_m * 64 + (lane >> 2);
#pragma unroll
    for (int nt = 0; nt < 4; nt++) {
        const int col = colBase + nt * 8;
        const float b0 = bias[col], b1 = bias[col + 1];
#pragma unroll
        for (int mt = 0; mt < 4; mt++) {
            float* p0 = C + (size_t)(rowBase + mt * 16) * N + col;
            float* p1 = C + (size_t)(rowBase + mt * 16 + 8) * N + col;
            *reinterpret_cast<float2*>(p0) = make_float2(acc[mt][nt][0] + b0, acc[mt][nt][1] + b1);
            *reinterpret_cast<float2*>(p1) = make_float2(acc[mt][nt][2] + b0, acc[mt][nt][3] + b1);
        }
    }
}

// ---------------------------------------------------------------------------
// f32 -> f16 conversion (grid-stride, float4 -> 4 halves)
// ---------------------------------------------------------------------------
__global__ __launch_bounds__(256)
void f2h_kernel(const float4* __restrict__ in, uint2* __restrict__ out, int n4)
{
    for (int i = blockIdx.x * blockDim.x + threadIdx.x; i < n4;
         i += gridDim.x * blockDim.x) {
        float4 v = in[i];
        __half2 h0 = __floats2half2_rn(v.x, v.y);
        __half2 h1 = __floats2half2_rn(v.z, v.w);
        uint2 o;
        o.x = *reinterpret_cast<uint32_t*>(&h0);
        o.y = *reinterpret_cast<uint32_t*>(&h1);
        out[i] = o;
    }
}

// ---------------------------------------------------------------------------
// Attention over the HEAD axis per token (faithful "buggy" einsum), reshape
// scramble fused into the store; output written as fp16 for the final GEMM.
// ---------------------------------------------------------------------------
__global__ __launch_bounds__(128)
void attn_kernel(const float* __restrict__ Q,
                 const float* __restrict__ K,
                 const float* __restrict__ V,
                 __half* __restrict__ Y)
{
    __shared__ float4 sQ[4][E_DIM / 4];
    __shared__ float4 sK[4][E_DIM / 4];
    __shared__ float4 sV[4][E_DIM / 4];

    const int w    = threadIdx.x >> 5;
    const int lane = threadIdx.x & 31;
    const int token = blockIdx.x * 4 + w;

    const size_t base4 = (size_t)token * (E_DIM / 4);
    const float4* Q4 = reinterpret_cast<const float4*>(Q) + base4;
    const float4* K4 = reinterpret_cast<const float4*>(K) + base4;
    const float4* V4 = reinterpret_cast<const float4*>(V) + base4;

#pragma unroll
    for (int c = 0; c < 8; c++) {
        sQ[w][lane + 32 * c] = Q4[lane + 32 * c];
        sK[w][lane + 32 * c] = K4[lane + 32 * c];
        sV[w][lane + 32 * c] = V4[lane + 32 * c];
    }
    __syncwarp();

    const int i    = lane >> 1;
    const int half = lane & 1;

    float e[8];
#pragma unroll
    for (int jj = 0; jj < 8; jj++) {
        const int j = half * 8 + jj;
        float dot = 0.0f;
#pragma unroll
        for (int d4 = 0; d4 < 16; d4++) {
            float4 a = sQ[w][i * 16 + d4];
            float4 b = sK[w][j * 16 + d4];
            dot += a.x * b.x + a.y * b.y + a.z * b.z + a.w * b.w;
        }
        e[jj] = dot * 0.03125f;   // 1/sqrt(1024)
    }

    float mx = e[0];
#pragma unroll
    for (int jj = 1; jj < 8; jj++) mx = fmaxf(mx, e[jj]);
    mx = fmaxf(mx, __shfl_xor_sync(0xffffffffu, mx, 1));

    float p[8], sum = 0.0f;
#pragma unroll
    for (int jj = 0; jj < 8; jj++) {
        p[jj] = __expf(e[jj] - mx);
        sum += p[jj];
    }
    sum += __shfl_xor_sync(0xffffffffu, sum, 1);
    const float inv = 1.0f / sum;

    float pj[16];
#pragma unroll
    for (int jj = 0; jj < 8; jj++) {
        float mine  = p[jj] * inv;
        float other = __shfl_xor_sync(0xffffffffu, mine, 1);
        pj[half * 8 + jj]       = mine;
        pj[(half ^ 1) * 8 + jj] = other;
    }

    const int n = token / S_LEN;
    const int s = token % S_LEN;
    __half* Yrow = Y + ((size_t)(n * S_LEN + i * 512 + (s >> 4)) * E_DIM)
                     + ((s & 15) * 64) + half * 32;

#pragma unroll
    for (int d4 = 0; d4 < 8; d4++) {
        float4 acc = make_float4(0.f, 0.f, 0.f, 0.f);
#pragma unroll
        for (int j = 0; j < 16; j++) {
            float4 v = sV[w][j * 16 + half * 8 + d4];
            acc.x += pj[j] * v.x;
            acc.y += pj[j] * v.y;
            acc.z += pj[j] * v.z;
            acc.w += pj[j] * v.w;
        }
        __half2 h0 = __floats2half2_rn(acc.x, acc.y);
        __half2 h1 = __floats2half2_rn(acc.z, acc.w);
        uint2 o;
        o.x = *reinterpret_cast<uint32_t*>(&h0);
        o.y = *reinterpret_cast<uint32_t*>(&h1);
        *reinterpret_cast<uint2*>(Yrow + d4 * 4) = o;
    }
}

// ---------------------------------------------------------------------------
// Launch
// ---------------------------------------------------------------------------
extern "C" void kernel_launch(void* const* d_in, const int* in_sizes, int n_in,
                              void* d_out, int out_size)
{
    const float* x  = (const float*)d_in[0];
    const float* Ws[4] = { (const float*)d_in[1], (const float*)d_in[2],
                           (const float*)d_in[3], (const float*)d_in[4] };
    const float* bq = (const float*)d_in[5];
    const float* bk = (const float*)d_in[6];
    const float* bv = (const float*)d_in[7];
    const float* bo = (const float*)d_in[8];
    float* out = (float*)d_out;

    __half *Xh, *Wh, *Yh;
    float *Q, *K, *V;
    cudaGetSymbolAddress((void**)&Xh, g_Xh);
    cudaGetSymbolAddress((void**)&Wh, g_Wh);
    cudaGetSymbolAddress((void**)&Yh, g_Yh);
    cudaGetSymbolAddress((void**)&Q,  g_Q);
    cudaGetSymbolAddress((void**)&K,  g_K);
    cudaGetSymbolAddress((void**)&V,  g_V);

    static bool attr_set = false;
    if (!attr_set) {
        cudaFuncSetAttribute(hgemm_bias_kernel,
                             cudaFuncAttributeMaxDynamicSharedMemorySize, SMEM_BYTES);
        attr_set = true;
    }

    // 1) convert operands to fp16
    const int xn4 = (M_TOT * E_DIM) / 4;
    const int wn4 = (E_DIM * E_DIM) / 4;
    f2h_kernel<<<2048, 256>>>((const float4*)x, (uint2*)Xh, xn4);
    for (int i = 0; i < 4; i++)
        f2h_kernel<<<512, 256>>>((const float4*)Ws[i],
                                 (uint2*)(Wh + (size_t)i * E_DIM * E_DIM), wn4);

    // 2) Q/K/V projections
    dim3 gblock(256);
    dim3 ggrid(E_DIM / BN, M_TOT / BM);
    hgemm_bias_kernel<<<ggrid, gblock, SMEM_BYTES>>>(Xh, Wh + 0 * (size_t)E_DIM * E_DIM, bq, Q, M_TOT, E_DIM, E_DIM);
    hgemm_bias_kernel<<<ggrid, gblock, SMEM_BYTES>>>(Xh, Wh + 1 * (size_t)E_DIM * E_DIM, bk, K, M_TOT, E_DIM, E_DIM);
    hgemm_bias_kernel<<<ggrid, gblock, SMEM_BYTES>>>(Xh, Wh + 2 * (size_t)E_DIM * E_DIM, bv, V, M_TOT, E_DIM, E_DIM);

    // 3) head-axis attention + scramble, fp16 output
    attn_kernel<<<M_TOT / 4, 128>>>(Q, K, V, Yh);

    // 4) output projection
    hgemm_bias_kernel<<<ggrid, gblock, SMEM_BYTES>>>(Yh, Wh + 3 * (size_t)E_DIM * E_DIM, bo, out, M_TOT, E_DIM, E_DIM);
}

// round 5
// speedup vs baseline: 4.9158x; 1.0918x over previous
#include <cuda_runtime.h>
#include <cuda_fp16.h>
#include <cstdint>

// ---------------------------------------------------------------------------
// Problem constants
// ---------------------------------------------------------------------------
#define NB     4
#define S_LEN  8192
#define E_DIM  1024
#define M_TOT  (NB * S_LEN)   // 32768

// ---------------------------------------------------------------------------
// GEMM tiling (fp16 mma.sync m16n8k16, ldmatrix fragments)
// ---------------------------------------------------------------------------
#define BM 128
#define BN 128
#define BKH 64                    // K-depth per stage, in halves (128 B rows)
#define LDH 72                    // padded smem row stride (halves)
#define TILE_H   (BM * LDH)
#define STG_H    (2 * TILE_H)
#define SMEM_BYTES (2 * STG_H * 2)   // 73728 B -> 2 CTAs/SM
#define NSTG (E_DIM / BKH)        // 16 k-stages

// ---------------------------------------------------------------------------
// Scratch
// ---------------------------------------------------------------------------
__device__ __half g_Xh[(size_t)M_TOT * E_DIM];
__device__ __half g_Wh[4][(size_t)E_DIM * E_DIM];
__device__ __half g_Qh[(size_t)M_TOT * E_DIM];
__device__ __half g_Kh[(size_t)M_TOT * E_DIM];
__device__ __half g_Vh[(size_t)M_TOT * E_DIM];
__device__ __half g_Yh[(size_t)M_TOT * E_DIM];

// ---------------------------------------------------------------------------
// Helpers
// ---------------------------------------------------------------------------
__device__ __forceinline__ void cp16(void* dst_smem, const void* src_gmem) {
    uint32_t d = (uint32_t)__cvta_generic_to_shared(dst_smem);
    asm volatile("cp.async.cg.shared.global [%0], [%1], 16;\n" :: "r"(d), "l"(src_gmem));
}
__device__ __forceinline__ void ldsm_x4(uint32_t& r0, uint32_t& r1,
                                        uint32_t& r2, uint32_t& r3, uint32_t addr) {
    asm volatile("ldmatrix.sync.aligned.m8n8.x4.shared.b16 {%0,%1,%2,%3}, [%4];"
        : "=r"(r0), "=r"(r1), "=r"(r2), "=r"(r3) : "r"(addr));
}
__device__ __forceinline__ void mma_f16(float c[4],
                                        uint32_t a0, uint32_t a1, uint32_t a2, uint32_t a3,
                                        uint32_t b0, uint32_t b1) {
    asm volatile(
        "mma.sync.aligned.m16n8k16.row.col.f32.f16.f16.f32 "
        "{%0,%1,%2,%3}, {%4,%5,%6,%7}, {%8,%9}, {%0,%1,%2,%3};\n"
        : "+f"(c[0]), "+f"(c[1]), "+f"(c[2]), "+f"(c[3])
        : "r"(a0), "r"(a1), "r"(a2), "r"(a3), "r"(b0), "r"(b1));
}

// ---------------------------------------------------------------------------
// fp16 tensor-core GEMM: C[M,N] = A[M,K] @ B[N,K]^T + bias[N]
// OutT = float (fp32 store) or __half (fp16 store).
// 256 threads = 8 warps, warp tile 64x32, block tile 128x128, BK=64 halves.
// ---------------------------------------------------------------------------
template <typename OutT>
__global__ __launch_bounds__(256, 2)
void hgemm_bias_kernel(const __half* __restrict__ A,
                       const __half* __restrict__ B,
                       const float* __restrict__ bias,
                       OutT* __restrict__ C,
                       int M, int N, int K)
{
    extern __shared__ __align__(128) __half smem[];
    const uint32_t smem_u32 = (uint32_t)__cvta_generic_to_shared(smem);

    const int tid    = threadIdx.x;
    const int lane   = tid & 31;
    const int warpId = tid >> 5;
    const int warp_m = warpId & 1;    // 64-row slab
    const int warp_n = warpId >> 1;   // 32-col slab

    const int blockN = blockIdx.x * BN;
    const int blockM = blockIdx.y * BM;

    const __half* Ab = A + (size_t)blockM * K;
    const __half* Bb = B + (size_t)blockN * K;

    const int sRow = tid >> 1;
    const int sC   = (tid & 1) * 4;

    float acc[4][4][4];
#pragma unroll
    for (int mt = 0; mt < 4; mt++)
#pragma unroll
        for (int nt = 0; nt < 4; nt++)
#pragma unroll
            for (int c = 0; c < 4; c++)
                acc[mt][nt][c] = 0.0f;

    auto load_stage = [&](int st) {
        const int k0 = st * BKH;
        __half* As = smem + (st & 1) * STG_H;
        __half* Bs = As + TILE_H;
#pragma unroll
        for (int c = 0; c < 4; c++) {
            cp16(As + sRow * LDH + (sC + c) * 8, Ab + (size_t)sRow * K + k0 + (sC + c) * 8);
            cp16(Bs + sRow * LDH + (sC + c) * 8, Bb + (size_t)sRow * K + k0 + (sC + c) * 8);
        }
        asm volatile("cp.async.commit_group;\n");
    };

    load_stage(0);
    load_stage(1);

    // ldmatrix per-lane base offsets (in halves)
    const int aBase = (warp_m * 64 + (lane & 15)) * LDH + (lane >> 4) * 8;
    const int bBase = (warp_n * 32 + (lane & 7) + ((lane >> 4) * 8)) * LDH
                    + ((lane >> 3) & 1) * 8;

    for (int it = 0; it < NSTG; it++) {
        if (it + 2 < NSTG) asm volatile("cp.async.wait_group 1;\n");
        else               asm volatile("cp.async.wait_group 0;\n");
        __syncthreads();

        const uint32_t As_u = smem_u32 + ((it & 1) * STG_H) * 2;
        const uint32_t Bs_u = As_u + TILE_H * 2;

#pragma unroll
        for (int ks = 0; ks < BKH / 16; ks++) {
            uint32_t af[4][4];
#pragma unroll
            for (int mt = 0; mt < 4; mt++)
                ldsm_x4(af[mt][0], af[mt][1], af[mt][2], af[mt][3],
                        As_u + (aBase + mt * 16 * LDH + ks * 16) * 2);

            uint32_t bf[4][2];
#pragma unroll
            for (int p = 0; p < 2; p++)
                ldsm_x4(bf[2 * p][0], bf[2 * p][1], bf[2 * p + 1][0], bf[2 * p + 1][1],
                        Bs_u + (bBase + p * 16 * LDH + ks * 16) * 2);

#pragma unroll
            for (int mt = 0; mt < 4; mt++)
#pragma unroll
                for (int nt = 0; nt < 4; nt++)
                    mma_f16(acc[mt][nt], af[mt][0], af[mt][1], af[mt][2], af[mt][3],
                            bf[nt][0], bf[nt][1]);
        }
        __syncthreads();

        if (it + 2 < NSTG) load_stage(it + 2);
    }

    // ---- epilogue ----
    const int colBase = blockN + warp_n * 32 + (lane & 3) * 2;
    const int rowBase = blockM + warp_m * 64 + (lane >> 2);
#pragma unroll
    for (int nt = 0; nt < 4; nt++) {
        const int col = colBase + nt * 8;
        const float b0 = bias[col], b1 = bias[col + 1];
#pragma unroll
        for (int mt = 0; mt < 4; mt++) {
            OutT* p0 = C + (size_t)(rowBase + mt * 16) * N + col;
            OutT* p1 = C + (size_t)(rowBase + mt * 16 + 8) * N + col;
            if constexpr (sizeof(OutT) == 4) {
                *reinterpret_cast<float2*>(p0) =
                    make_float2(acc[mt][nt][0] + b0, acc[mt][nt][1] + b1);
                *reinterpret_cast<float2*>(p1) =
                    make_float2(acc[mt][nt][2] + b0, acc[mt][nt][3] + b1);
            } else {
                __half2 h0 = __floats2half2_rn(acc[mt][nt][0] + b0, acc[mt][nt][1] + b1);
                __half2 h1 = __floats2half2_rn(acc[mt][nt][2] + b0, acc[mt][nt][3] + b1);
                *reinterpret_cast<__half2*>(p0) = h0;
                *reinterpret_cast<__half2*>(p1) = h1;
            }
        }
    }
}

// ---------------------------------------------------------------------------
// f32 -> f16 conversion
// ---------------------------------------------------------------------------
__global__ __launch_bounds__(256)
void f2h_kernel(const float4* __restrict__ in, uint2* __restrict__ out, int n4)
{
    for (int i = blockIdx.x * blockDim.x + threadIdx.x; i < n4;
         i += gridDim.x * blockDim.x) {
        float4 v = in[i];
        __half2 h0 = __floats2half2_rn(v.x, v.y);
        __half2 h1 = __floats2half2_rn(v.z, v.w);
        uint2 o;
        o.x = *reinterpret_cast<uint32_t*>(&h0);
        o.y = *reinterpret_cast<uint32_t*>(&h1);
        out[i] = o;
    }
}

// ---------------------------------------------------------------------------
// Head-axis attention per token (faithful "buggy" einsum), fp16 in/out,
// fp32 accumulation, reshape scramble fused into the store.
// One warp per token; lane l owns (i = l>>1, half = l&1).
// ---------------------------------------------------------------------------
__device__ __forceinline__ float dot8h(uint4 a, uint4 b) {
    const __half2* ah = reinterpret_cast<const __half2*>(&a);
    const __half2* bh = reinterpret_cast<const __half2*>(&b);
    float s = 0.0f;
#pragma unroll
    for (int t = 0; t < 4; t++) {
        float2 fa = __half22float2(ah[t]);
        float2 fb = __half22float2(bh[t]);
        s += fa.x * fb.x + fa.y * fb.y;
    }
    return s;
}

__global__ __launch_bounds__(128)
void attn_kernel(const __half* __restrict__ Q,
                 const __half* __restrict__ K,
                 const __half* __restrict__ V,
                 __half* __restrict__ Y)
{
    __shared__ uint4 sQ[4][E_DIM / 8];
    __shared__ uint4 sK[4][E_DIM / 8];
    __shared__ uint4 sV[4][E_DIM / 8];

    const int w    = threadIdx.x >> 5;
    const int lane = threadIdx.x & 31;
    const int token = blockIdx.x * 4 + w;

    const uint4* Q4 = reinterpret_cast<const uint4*>(Q + (size_t)token * E_DIM);
    const uint4* K4 = reinterpret_cast<const uint4*>(K + (size_t)token * E_DIM);
    const uint4* V4 = reinterpret_cast<const uint4*>(V + (size_t)token * E_DIM);

#pragma unroll
    for (int c = 0; c < 4; c++) {
        sQ[w][lane + 32 * c] = Q4[lane + 32 * c];
        sK[w][lane + 32 * c] = K4[lane + 32 * c];
        sV[w][lane + 32 * c] = V4[lane + 32 * c];
    }
    __syncwarp();

    const int i    = lane >> 1;
    const int half = lane & 1;

    // hoist this lane's Q row (64 halves = 8 uint4)
    uint4 q[8];
#pragma unroll
    for (int c = 0; c < 8; c++) q[c] = sQ[w][i * 8 + c];

    float e[8];
#pragma unroll
    for (int jj = 0; jj < 8; jj++) {
        const int j = half * 8 + jj;
        float dot = 0.0f;
#pragma unroll
        for (int c = 0; c < 8; c++)
            dot += dot8h(q[c], sK[w][j * 8 + c]);
        e[jj] = dot * 0.03125f;   // 1/sqrt(1024)
    }

    float mx = e[0];
#pragma unroll
    for (int jj = 1; jj < 8; jj++) mx = fmaxf(mx, e[jj]);
    mx = fmaxf(mx, __shfl_xor_sync(0xffffffffu, mx, 1));

    float p[8], sum = 0.0f;
#pragma unroll
    for (int jj = 0; jj < 8; jj++) {
        p[jj] = __expf(e[jj] - mx);
        sum += p[jj];
    }
    sum += __shfl_xor_sync(0xffffffffu, sum, 1);
    const float inv = 1.0f / sum;

    float pj[16];
#pragma unroll
    for (int jj = 0; jj < 8; jj++) {
        float mine  = p[jj] * inv;
        float other = __shfl_xor_sync(0xffffffffu, mine, 1);
        pj[half * 8 + jj]       = mine;
        pj[(half ^ 1) * 8 + jj] = other;
    }

    const int n = token / S_LEN;
    const int s = token % S_LEN;
    __half* Yrow = Y + ((size_t)(n * S_LEN + i * 512 + (s >> 4)) * E_DIM)
                     + ((s & 15) * 64) + half * 32;

#pragma unroll
    for (int d8 = 0; d8 < 4; d8++) {      // 8 output halves per group
        float acc[8];
#pragma unroll
        for (int t = 0; t < 8; t++) acc[t] = 0.0f;
#pragma unroll
        for (int j = 0; j < 16; j++) {
            uint4 v = sV[w][j * 8 + half * 4 + d8];
            const __half2* vh = reinterpret_cast<const __half2*>(&v);
#pragma unroll
            for (int t = 0; t < 4; t++) {
                float2 fv = __half22float2(vh[t]);
                acc[2 * t]     += pj[j] * fv.x;
                acc[2 * t + 1] += pj[j] * fv.y;
            }
        }
        uint4 o;
        __half2 h0 = __floats2half2_rn(acc[0], acc[1]);
        __half2 h1 = __floats2half2_rn(acc[2], acc[3]);
        __half2 h2 = __floats2half2_rn(acc[4], acc[5]);
        __half2 h3 = __floats2half2_rn(acc[6], acc[7]);
        o.x = *reinterpret_cast<uint32_t*>(&h0);
        o.y = *reinterpret_cast<uint32_t*>(&h1);
        o.z = *reinterpret_cast<uint32_t*>(&h2);
        o.w = *reinterpret_cast<uint32_t*>(&h3);
        *reinterpret_cast<uint4*>(Yrow + d8 * 8) = o;
    }
}

// ---------------------------------------------------------------------------
// Launch
// ---------------------------------------------------------------------------
extern "C" void kernel_launch(void* const* d_in, const int* in_sizes, int n_in,
                              void* d_out, int out_size)
{
    const float* x  = (const float*)d_in[0];
    const float* Ws[4] = { (const float*)d_in[1], (const float*)d_in[2],
                           (const float*)d_in[3], (const float*)d_in[4] };
    const float* bq = (const float*)d_in[5];
    const float* bk = (const float*)d_in[6];
    const float* bv = (const float*)d_in[7];
    const float* bo = (const float*)d_in[8];
    float* out = (float*)d_out;

    __half *Xh, *Wh, *Qh, *Kh, *Vh, *Yh;
    cudaGetSymbolAddress((void**)&Xh, g_Xh);
    cudaGetSymbolAddress((void**)&Wh, g_Wh);
    cudaGetSymbolAddress((void**)&Qh, g_Qh);
    cudaGetSymbolAddress((void**)&Kh, g_Kh);
    cudaGetSymbolAddress((void**)&Vh, g_Vh);
    cudaGetSymbolAddress((void**)&Yh, g_Yh);

    static bool attr_set = false;
    if (!attr_set) {
        cudaFuncSetAttribute(hgemm_bias_kernel<__half>,
                             cudaFuncAttributeMaxDynamicSharedMemorySize, SMEM_BYTES);
        cudaFuncSetAttribute(hgemm_bias_kernel<float>,
                             cudaFuncAttributeMaxDynamicSharedMemorySize, SMEM_BYTES);
        attr_set = true;
    }

    // 1) convert operands to fp16
    const int xn4 = (M_TOT * E_DIM) / 4;
    const int wn4 = (E_DIM * E_DIM) / 4;
    f2h_kernel<<<2048, 256>>>((const float4*)x, (uint2*)Xh, xn4);
    for (int i = 0; i < 4; i++)
        f2h_kernel<<<512, 256>>>((const float4*)Ws[i],
                                 (uint2*)(Wh + (size_t)i * E_DIM * E_DIM), wn4);

    // 2) Q/K/V projections (fp16 outputs)
    dim3 gblock(256);
    dim3 ggrid(E_DIM / BN, M_TOT / BM);
    hgemm_bias_kernel<__half><<<ggrid, gblock, SMEM_BYTES>>>(
        Xh, Wh + 0 * (size_t)E_DIM * E_DIM, bq, Qh, M_TOT, E_DIM, E_DIM);
    hgemm_bias_kernel<__half><<<ggrid, gblock, SMEM_BYTES>>>(
        Xh, Wh + 1 * (size_t)E_DIM * E_DIM, bk, Kh, M_TOT, E_DIM, E_DIM);
    hgemm_bias_kernel<__half><<<ggrid, gblock, SMEM_BYTES>>>(
        Xh, Wh + 2 * (size_t)E_DIM * E_DIM, bv, Vh, M_TOT, E_DIM, E_DIM);

    // 3) head-axis attention + scramble (fp16 in/out)
    attn_kernel<<<M_TOT / 4, 128>>>(Qh, Kh, Vh, Yh);

    // 4) output projection (fp32 out)
    hgemm_bias_kernel<float><<<ggrid, gblock, SMEM_BYTES>>>(
        Yh, Wh + 3 * (size_t)E_DIM * E_DIM, bo, out, M_TOT, E_DIM, E_DIM);
}

// round 6
// speedup vs baseline: 6.5727x; 1.3370x over previous
#include <cuda_runtime.h>
#include <cuda_fp16.h>
#include <cstdint>

// ---------------------------------------------------------------------------
// Problem constants
// ---------------------------------------------------------------------------
#define NB     4
#define S_LEN  8192
#define E_DIM  1024
#define M_TOT  (NB * S_LEN)   // 32768

// ---------------------------------------------------------------------------
// GEMM tiling: block 128x256, warp tile 64x64, BK=64 halves, 3-stage pipeline
// ---------------------------------------------------------------------------
#define BM 128
#define BN 256
#define BKH 64                     // K per stage in halves (128 B rows)
#define LDH 72                     // padded smem row stride (halves)
#define A_H (BM * LDH)             // 9216 halves
#define B_H (BN * LDH)             // 18432 halves
#define STG_H (A_H + B_H)          // 27648 halves / stage
#define NSTAGE 3
#define SMEM_BYTES (NSTAGE * STG_H * 2)   // 165888 B
#define NSTG (E_DIM / BKH)         // 16 k-stages

// ---------------------------------------------------------------------------
// Scratch
// ---------------------------------------------------------------------------
__device__ __half g_Xh[(size_t)M_TOT * E_DIM];
__device__ __half g_Wh[4][(size_t)E_DIM * E_DIM];
__device__ __half g_Qh[(size_t)M_TOT * E_DIM];
__device__ __half g_Kh[(size_t)M_TOT * E_DIM];
__device__ __half g_Vh[(size_t)M_TOT * E_DIM];
__device__ __half g_Yh[(size_t)M_TOT * E_DIM];

// ---------------------------------------------------------------------------
// Helpers
// ---------------------------------------------------------------------------
__device__ __forceinline__ void cp16(void* dst_smem, const void* src_gmem) {
    uint32_t d = (uint32_t)__cvta_generic_to_shared(dst_smem);
    asm volatile("cp.async.cg.shared.global [%0], [%1], 16;\n" :: "r"(d), "l"(src_gmem));
}
__device__ __forceinline__ void ldsm_x4(uint32_t& r0, uint32_t& r1,
                                        uint32_t& r2, uint32_t& r3, uint32_t addr) {
    asm volatile("ldmatrix.sync.aligned.m8n8.x4.shared.b16 {%0,%1,%2,%3}, [%4];"
        : "=r"(r0), "=r"(r1), "=r"(r2), "=r"(r3) : "r"(addr));
}
__device__ __forceinline__ void mma_f16(float c[4],
                                        uint32_t a0, uint32_t a1, uint32_t a2, uint32_t a3,
                                        uint32_t b0, uint32_t b1) {
    asm volatile(
        "mma.sync.aligned.m16n8k16.row.col.f32.f16.f16.f32 "
        "{%0,%1,%2,%3}, {%4,%5,%6,%7}, {%8,%9}, {%0,%1,%2,%3};\n"
        : "+f"(c[0]), "+f"(c[1]), "+f"(c[2]), "+f"(c[3])
        : "r"(a0), "r"(a1), "r"(a2), "r"(a3), "r"(b0), "r"(b1));
}

// ---------------------------------------------------------------------------
// fp16 tensor-core GEMM: C[M,N] = A[M,K] @ B[N,K]^T + bias[N]
// 256 threads = 8 warps (2 warp_m x 4 warp_n), warp tile 64x64.
// ---------------------------------------------------------------------------
template <typename OutT>
__global__ __launch_bounds__(256, 1)
void hgemm_bias_kernel(const __half* __restrict__ A,
                       const __half* __restrict__ B,
                       const float* __restrict__ bias,
                       OutT* __restrict__ C,
                       int M, int N, int K)
{
    extern __shared__ __align__(128) __half smem[];
    const uint32_t smem_u32 = (uint32_t)__cvta_generic_to_shared(smem);

    const int tid    = threadIdx.x;
    const int lane   = tid & 31;
    const int warpId = tid >> 5;
    const int warp_m = warpId & 1;    // 64-row slab
    const int warp_n = warpId >> 1;   // 64-col slab (0..3)

    const int blockN = blockIdx.x * BN;
    const int blockM = blockIdx.y * BM;

    const __half* Ab = A + (size_t)blockM * K;
    const __half* Bb = B + (size_t)blockN * K;

    float acc[4][8][4];
#pragma unroll
    for (int mt = 0; mt < 4; mt++)
#pragma unroll
        for (int nt = 0; nt < 8; nt++)
#pragma unroll
            for (int c = 0; c < 4; c++)
                acc[mt][nt][c] = 0.0f;

    // staging: rows of 8x16B chunks. A: 1024 chunks (4/thr), B: 2048 (8/thr)
    auto load_stage = [&](int st, int slot) {
        const int k0 = st * BKH;
        __half* As = smem + slot * STG_H;
        __half* Bs = As + A_H;
#pragma unroll
        for (int i = 0; i < 4; i++) {
            int idx = tid + i * 256;
            int row = idx >> 3, c = idx & 7;
            cp16(As + row * LDH + c * 8, Ab + (size_t)row * K + k0 + c * 8);
        }
#pragma unroll
        for (int i = 0; i < 8; i++) {
            int idx = tid + i * 256;
            int row = idx >> 3, c = idx & 7;
            cp16(Bs + row * LDH + c * 8, Bb + (size_t)row * K + k0 + c * 8);
        }
        asm volatile("cp.async.commit_group;\n");
    };

    load_stage(0, 0);
    load_stage(1, 1);

    // ldmatrix per-lane base offsets (halves)
    const int aBase = (warp_m * 64 + (lane & 15)) * LDH + (lane >> 4) * 8;
    const int bBase = (warp_n * 64 + (lane & 7) + ((lane >> 4) * 8)) * LDH
                    + ((lane >> 3) & 1) * 8;

    int cs = 0, ls = 2;
    for (int it = 0; it < NSTG; it++) {
        if (it + 2 < NSTG) asm volatile("cp.async.wait_group 1;\n");
        else               asm volatile("cp.async.wait_group 0;\n");
        __syncthreads();

        if (it + 2 < NSTG) load_stage(it + 2, ls);

        const uint32_t As_u = smem_u32 + (cs * STG_H) * 2;
        const uint32_t Bs_u = As_u + A_H * 2;

#pragma unroll
        for (int ks = 0; ks < BKH / 16; ks++) {
            uint32_t af[4][4];
#pragma unroll
            for (int mt = 0; mt < 4; mt++)
                ldsm_x4(af[mt][0], af[mt][1], af[mt][2], af[mt][3],
                        As_u + (aBase + mt * 16 * LDH + ks * 16) * 2);

            uint32_t bf[8][2];
#pragma unroll
            for (int p = 0; p < 4; p++)
                ldsm_x4(bf[2 * p][0], bf[2 * p][1], bf[2 * p + 1][0], bf[2 * p + 1][1],
                        Bs_u + (bBase + p * 16 * LDH + ks * 16) * 2);

#pragma unroll
            for (int mt = 0; mt < 4; mt++)
#pragma unroll
                for (int nt = 0; nt < 8; nt++)
                    mma_f16(acc[mt][nt], af[mt][0], af[mt][1], af[mt][2], af[mt][3],
                            bf[nt][0], bf[nt][1]);
        }

        cs = (cs == NSTAGE - 1) ? 0 : cs + 1;
        ls = (ls == NSTAGE - 1) ? 0 : ls + 1;
    }

    // ---- epilogue ----
    const int colBase = blockN + warp_n * 64 + (lane & 3) * 2;
    const int rowBase = blockM + warp_m * 64 + (lane >> 2);
#pragma unroll
    for (int nt = 0; nt < 8; nt++) {
        const int col = colBase + nt * 8;
        const float b0 = bias[col], b1 = bias[col + 1];
#pragma unroll
        for (int mt = 0; mt < 4; mt++) {
            OutT* p0 = C + (size_t)(rowBase + mt * 16) * N + col;
            OutT* p1 = C + (size_t)(rowBase + mt * 16 + 8) * N + col;
            if constexpr (sizeof(OutT) == 4) {
                *reinterpret_cast<float2*>(p0) =
                    make_float2(acc[mt][nt][0] + b0, acc[mt][nt][1] + b1);
                *reinterpret_cast<float2*>(p1) =
                    make_float2(acc[mt][nt][2] + b0, acc[mt][nt][3] + b1);
            } else {
                __half2 h0 = __floats2half2_rn(acc[mt][nt][0] + b0, acc[mt][nt][1] + b1);
                __half2 h1 = __floats2half2_rn(acc[mt][nt][2] + b0, acc[mt][nt][3] + b1);
                *reinterpret_cast<__half2*>(p0) = h0;
                *reinterpret_cast<__half2*>(p1) = h1;
            }
        }
    }
}

// ---------------------------------------------------------------------------
// f32 -> f16 conversion
// ---------------------------------------------------------------------------
__global__ __launch_bounds__(256)
void f2h_kernel(const float4* __restrict__ in, uint2* __restrict__ out, int n4)
{
    for (int i = blockIdx.x * blockDim.x + threadIdx.x; i < n4;
         i += gridDim.x * blockDim.x) {
        float4 v = in[i];
        __half2 h0 = __floats2half2_rn(v.x, v.y);
        __half2 h1 = __floats2half2_rn(v.z, v.w);
        uint2 o;
        o.x = *reinterpret_cast<uint32_t*>(&h0);
        o.y = *reinterpret_cast<uint32_t*>(&h1);
        out[i] = o;
    }
}

// ---------------------------------------------------------------------------
// Head-axis attention per token (faithful "buggy" einsum), fp16 in/out,
// fp32 accumulation, reshape scramble fused into the store.
// ---------------------------------------------------------------------------
__device__ __forceinline__ float dot8h(uint4 a, uint4 b) {
    const __half2* ah = reinterpret_cast<const __half2*>(&a);
    const __half2* bh = reinterpret_cast<const __half2*>(&b);
    float s = 0.0f;
#pragma unroll
    for (int t = 0; t < 4; t++) {
        float2 fa = __half22float2(ah[t]);
        float2 fb = __half22float2(bh[t]);
        s += fa.x * fb.x + fa.y * fb.y;
    }
    return s;
}

__global__ __launch_bounds__(128)
void attn_kernel(const __half* __restrict__ Q,
                 const __half* __restrict__ K,
                 const __half* __restrict__ V,
                 __half* __restrict__ Y)
{
    __shared__ uint4 sQ[4][E_DIM / 8];
    __shared__ uint4 sK[4][E_DIM / 8];
    __shared__ uint4 sV[4][E_DIM / 8];

    const int w    = threadIdx.x >> 5;
    const int lane = threadIdx.x & 31;
    const int token = blockIdx.x * 4 + w;

    const uint4* Q4 = reinterpret_cast<const uint4*>(Q + (size_t)token * E_DIM);
    const uint4* K4 = reinterpret_cast<const uint4*>(K + (size_t)token * E_DIM);
    const uint4* V4 = reinterpret_cast<const uint4*>(V + (size_t)token * E_DIM);

#pragma unroll
    for (int c = 0; c < 4; c++) {
        sQ[w][lane + 32 * c] = Q4[lane + 32 * c];
        sK[w][lane + 32 * c] = K4[lane + 32 * c];
        sV[w][lane + 32 * c] = V4[lane + 32 * c];
    }
    __syncwarp();

    const int i    = lane >> 1;
    const int half = lane & 1;

    uint4 q[8];
#pragma unroll
    for (int c = 0; c < 8; c++) q[c] = sQ[w][i * 8 + c];

    float e[8];
#pragma unroll
    for (int jj = 0; jj < 8; jj++) {
        const int j = half * 8 + jj;
        float dot = 0.0f;
#pragma unroll
        for (int c = 0; c < 8; c++)
            dot += dot8h(q[c], sK[w][j * 8 + c]);
        e[jj] = dot * 0.03125f;   // 1/sqrt(1024)
    }

    float mx = e[0];
#pragma unroll
    for (int jj = 1; jj < 8; jj++) mx = fmaxf(mx, e[jj]);
    mx = fmaxf(mx, __shfl_xor_sync(0xffffffffu, mx, 1));

    float p[8], sum = 0.0f;
#pragma unroll
    for (int jj = 0; jj < 8; jj++) {
        p[jj] = __expf(e[jj] - mx);
        sum += p[jj];
    }
    sum += __shfl_xor_sync(0xffffffffu, sum, 1);
    const float inv = 1.0f / sum;

    float pj[16];
#pragma unroll
    for (int jj = 0; jj < 8; jj++) {
        float mine  = p[jj] * inv;
        float other = __shfl_xor_sync(0xffffffffu, mine, 1);
        pj[half * 8 + jj]       = mine;
        pj[(half ^ 1) * 8 + jj] = other;
    }

    const int n = token / S_LEN;
    const int s = token % S_LEN;
    __half* Yrow = Y + ((size_t)(n * S_LEN + i * 512 + (s >> 4)) * E_DIM)
                     + ((s & 15) * 64) + half * 32;

#pragma unroll
    for (int d8 = 0; d8 < 4; d8++) {
        float acc[8];
#pragma unroll
        for (int t = 0; t < 8; t++) acc[t] = 0.0f;
#pragma unroll
        for (int j = 0; j < 16; j++) {
            uint4 v = sV[w][j * 8 + half * 4 + d8];
            const __half2* vh = reinterpret_cast<const __half2*>(&v);
#pragma unroll
            for (int t = 0; t < 4; t++) {
                float2 fv = __half22float2(vh[t]);
                acc[2 * t]     += pj[j] * fv.x;
                acc[2 * t + 1] += pj[j] * fv.y;
            }
        }
        uint4 o;
        __half2 h0 = __floats2half2_rn(acc[0], acc[1]);
        __half2 h1 = __floats2half2_rn(acc[2], acc[3]);
        __half2 h2 = __floats2half2_rn(acc[4], acc[5]);
        __half2 h3 = __floats2half2_rn(acc[6], acc[7]);
        o.x = *reinterpret_cast<uint32_t*>(&h0);
        o.y = *reinterpret_cast<uint32_t*>(&h1);
        o.z = *reinterpret_cast<uint32_t*>(&h2);
        o.w = *reinterpret_cast<uint32_t*>(&h3);
        *reinterpret_cast<uint4*>(Yrow + d8 * 8) = o;
    }
}

// ---------------------------------------------------------------------------
// Launch
// ---------------------------------------------------------------------------
extern "C" void kernel_launch(void* const* d_in, const int* in_sizes, int n_in,
                              void* d_out, int out_size)
{
    const float* x  = (const float*)d_in[0];
    const float* Ws[4] = { (const float*)d_in[1], (const float*)d_in[2],
                           (const float*)d_in[3], (const float*)d_in[4] };
    const float* bq = (const float*)d_in[5];
    const float* bk = (const float*)d_in[6];
    const float* bv = (const float*)d_in[7];
    const float* bo = (const float*)d_in[8];
    float* out = (float*)d_out;

    __half *Xh, *Wh, *Qh, *Kh, *Vh, *Yh;
    cudaGetSymbolAddress((void**)&Xh, g_Xh);
    cudaGetSymbolAddress((void**)&Wh, g_Wh);
    cudaGetSymbolAddress((void**)&Qh, g_Qh);
    cudaGetSymbolAddress((void**)&Kh, g_Kh);
    cudaGetSymbolAddress((void**)&Vh, g_Vh);
    cudaGetSymbolAddress((void**)&Yh, g_Yh);

    static bool attr_set = false;
    if (!attr_set) {
        cudaFuncSetAttribute(hgemm_bias_kernel<__half>,
                             cudaFuncAttributeMaxDynamicSharedMemorySize, SMEM_BYTES);
        cudaFuncSetAttribute(hgemm_bias_kernel<float>,
                             cudaFuncAttributeMaxDynamicSharedMemorySize, SMEM_BYTES);
        attr_set = true;
    }

    // 1) convert operands to fp16
    const int xn4 = (M_TOT * E_DIM) / 4;
    const int wn4 = (E_DIM * E_DIM) / 4;
    f2h_kernel<<<2048, 256>>>((const float4*)x, (uint2*)Xh, xn4);
    for (int i = 0; i < 4; i++)
        f2h_kernel<<<512, 256>>>((const float4*)Ws[i],
                                 (uint2*)(Wh + (size_t)i * E_DIM * E_DIM), wn4);

    // 2) Q/K/V projections (fp16 outputs)
    dim3 gblock(256);
    dim3 ggrid(E_DIM / BN, M_TOT / BM);
    hgemm_bias_kernel<__half><<<ggrid, gblock, SMEM_BYTES>>>(
        Xh, Wh + 0 * (size_t)E_DIM * E_DIM, bq, Qh, M_TOT, E_DIM, E_DIM);
    hgemm_bias_kernel<__half><<<ggrid, gblock, SMEM_BYTES>>>(
        Xh, Wh + 1 * (size_t)E_DIM * E_DIM, bk, Kh, M_TOT, E_DIM, E_DIM);
    hgemm_bias_kernel<__half><<<ggrid, gblock, SMEM_BYTES>>>(
        Xh, Wh + 2 * (size_t)E_DIM * E_DIM, bv, Vh, M_TOT, E_DIM, E_DIM);

    // 3) head-axis attention + scramble (fp16 in/out)
    attn_kernel<<<M_TOT / 4, 128>>>(Qh, Kh, Vh, Yh);

    // 4) output projection (fp32 out)
    hgemm_bias_kernel<float><<<ggrid, gblock, SMEM_BYTES>>>(
        Yh, Wh + 3 * (size_t)E_DIM * E_DIM, bo, out, M_TOT, E_DIM, E_DIM);
}

// round 8
// speedup vs baseline: 6.5998x; 1.0041x over previous
#include <cuda_runtime.h>
#include <cuda_fp16.h>
#include <cstdint>

// ---------------------------------------------------------------------------
// Problem constants
// ---------------------------------------------------------------------------
#define NB     4
#define S_LEN  8192
#define E_DIM  1024
#define M_TOT  (NB * S_LEN)   // 32768

// ---------------------------------------------------------------------------
// GEMM tiling: block 128x256, warp tile 64x64, BK=64 halves, 4-stage pipeline
// ---------------------------------------------------------------------------
#define BM 128
#define BN 256
#define BKH 64                     // K per stage in halves (128 B rows)
#define LDH 72                     // padded smem row stride (halves)
#define A_H (BM * LDH)             // 9216 halves
#define B_H (BN * LDH)             // 18432 halves
#define STG_H (A_H + B_H)          // 27648 halves / stage
#define NSTAGE 4
#define SMEM_BYTES (NSTAGE * STG_H * 2)   // 221184 B
#define NSTG (E_DIM / BKH)         // 16 k-stages

// ---------------------------------------------------------------------------
// Scratch
// ---------------------------------------------------------------------------
__device__ __half g_Xh[(size_t)M_TOT * E_DIM];
__device__ __half g_Wh[4][(size_t)E_DIM * E_DIM];
__device__ __half g_Qh[(size_t)M_TOT * E_DIM];
__device__ __half g_Kh[(size_t)M_TOT * E_DIM];
__device__ __half g_Vh[(size_t)M_TOT * E_DIM];
__device__ __half g_Yh[(size_t)M_TOT * E_DIM];

// ---------------------------------------------------------------------------
// Helpers
// ---------------------------------------------------------------------------
__device__ __forceinline__ void cp16(void* dst_smem, const void* src_gmem) {
    uint32_t d = (uint32_t)__cvta_generic_to_shared(dst_smem);
    asm volatile("cp.async.cg.shared.global [%0], [%1], 16;\n" :: "r"(d), "l"(src_gmem));
}
__device__ __forceinline__ void ldsm_x4(uint32_t& r0, uint32_t& r1,
                                        uint32_t& r2, uint32_t& r3, uint32_t addr) {
    asm volatile("ldmatrix.sync.aligned.m8n8.x4.shared.b16 {%0,%1,%2,%3}, [%4];"
        : "=r"(r0), "=r"(r1), "=r"(r2), "=r"(r3) : "r"(addr));
}
__device__ __forceinline__ void mma_f16(float c[4],
                                        uint32_t a0, uint32_t a1, uint32_t a2, uint32_t a3,
                                        uint32_t b0, uint32_t b1) {
    asm volatile(
        "mma.sync.aligned.m16n8k16.row.col.f32.f16.f16.f32 "
        "{%0,%1,%2,%3}, {%4,%5,%6,%7}, {%8,%9}, {%0,%1,%2,%3};\n"
        : "+f"(c[0]), "+f"(c[1]), "+f"(c[2]), "+f"(c[3])
        : "r"(a0), "r"(a1), "r"(a2), "r"(a3), "r"(b0), "r"(b1));
}

// ---------------------------------------------------------------------------
// fp16 tensor-core GEMM: C[M,N] = A[M,K] @ B[N,K]^T + bias[N]
// 256 threads = 8 warps (2 warp_m x 4 warp_n), warp tile 64x64.
// 4-stage cp.async pipeline + ks-level fragment double buffering.
// ---------------------------------------------------------------------------
template <typename OutT>
__global__ __launch_bounds__(256, 1)
void hgemm_bias_kernel(const __half* __restrict__ A,
                       const __half* __restrict__ B,
                       const float* __restrict__ bias,
                       OutT* __restrict__ C,
                       int M, int N, int K)
{
    extern __shared__ __align__(128) __half smem[];
    const uint32_t smem_u32 = (uint32_t)__cvta_generic_to_shared(smem);

    const int tid    = threadIdx.x;
    const int lane   = tid & 31;
    const int warpId = tid >> 5;
    const int warp_m = warpId & 1;    // 64-row slab
    const int warp_n = warpId >> 1;   // 64-col slab (0..3)

    const int blockN = blockIdx.x * BN;
    const int blockM = blockIdx.y * BM;

    const __half* Ab = A + (size_t)blockM * K;
    const __half* Bb = B + (size_t)blockN * K;

    float acc[4][8][4];
#pragma unroll
    for (int mt = 0; mt < 4; mt++)
#pragma unroll
        for (int nt = 0; nt < 8; nt++)
#pragma unroll
            for (int c = 0; c < 4; c++)
                acc[mt][nt][c] = 0.0f;

    auto load_stage = [&](int st, int slot) {
        const int k0 = st * BKH;
        __half* As = smem + slot * STG_H;
        __half* Bs = As + A_H;
#pragma unroll
        for (int i = 0; i < 4; i++) {
            int idx = tid + i * 256;
            int row = idx >> 3, c = idx & 7;
            cp16(As + row * LDH + c * 8, Ab + (size_t)row * K + k0 + c * 8);
        }
#pragma unroll
        for (int i = 0; i < 8; i++) {
            int idx = tid + i * 256;
            int row = idx >> 3, c = idx & 7;
            cp16(Bs + row * LDH + c * 8, Bb + (size_t)row * K + k0 + c * 8);
        }
        asm volatile("cp.async.commit_group;\n");
    };

    load_stage(0, 0);
    load_stage(1, 1);
    load_stage(2, 2);

    // ldmatrix per-lane base offsets (halves)
    const int aBase = (warp_m * 64 + (lane & 15)) * LDH + (lane >> 4) * 8;
    const int bBase = (warp_n * 64 + (lane & 7) + ((lane >> 4) * 8)) * LDH
                    + ((lane >> 3) & 1) * 8;

    uint32_t af[2][4][4];
    uint32_t bf[2][8][2];

    int cs = 0;
    for (int it = 0; it < NSTG; it++) {
        if (it + 3 < NSTG)       asm volatile("cp.async.wait_group 2;\n");
        else if (it + 2 < NSTG)  asm volatile("cp.async.wait_group 2;\n");
        else if (it + 1 < NSTG)  asm volatile("cp.async.wait_group 1;\n");
        else                     asm volatile("cp.async.wait_group 0;\n");
        __syncthreads();

        if (it + 3 < NSTG) load_stage(it + 3, (it + 3) & (NSTAGE - 1));

        const uint32_t As_u = smem_u32 + (cs * STG_H) * 2;
        const uint32_t Bs_u = As_u + A_H * 2;

        // prefetch fragments for ks=0
#pragma unroll
        for (int mt = 0; mt < 4; mt++)
            ldsm_x4(af[0][mt][0], af[0][mt][1], af[0][mt][2], af[0][mt][3],
                    As_u + (aBase + mt * 16 * LDH) * 2);
#pragma unroll
        for (int p = 0; p < 4; p++)
            ldsm_x4(bf[0][2 * p][0], bf[0][2 * p][1],
                    bf[0][2 * p + 1][0], bf[0][2 * p + 1][1],
                    Bs_u + (bBase + p * 16 * LDH) * 2);

#pragma unroll
        for (int ks = 0; ks < BKH / 16; ks++) {
            const int cur = ks & 1;
            const int nxt = cur ^ 1;
            if (ks + 1 < BKH / 16) {
#pragma unroll
                for (int mt = 0; mt < 4; mt++)
                    ldsm_x4(af[nxt][mt][0], af[nxt][mt][1], af[nxt][mt][2], af[nxt][mt][3],
                            As_u + (aBase + mt * 16 * LDH + (ks + 1) * 16) * 2);
#pragma unroll
                for (int p = 0; p < 4; p++)
                    ldsm_x4(bf[nxt][2 * p][0], bf[nxt][2 * p][1],
                            bf[nxt][2 * p + 1][0], bf[nxt][2 * p + 1][1],
                            Bs_u + (bBase + p * 16 * LDH + (ks + 1) * 16) * 2);
            }
#pragma unroll
            for (int mt = 0; mt < 4; mt++)
#pragma unroll
                for (int nt = 0; nt < 8; nt++)
                    mma_f16(acc[mt][nt],
                            af[cur][mt][0], af[cur][mt][1], af[cur][mt][2], af[cur][mt][3],
                            bf[cur][nt][0], bf[cur][nt][1]);
        }

        cs = (cs + 1) & (NSTAGE - 1);
    }

    // ---- epilogue ----
    const int colBase = blockN + warp_n * 64 + (lane & 3) * 2;
    const int rowBase = blockM + warp_m * 64 + (lane >> 2);
#pragma unroll
    for (int nt = 0; nt < 8; nt++) {
        const int col = colBase + nt * 8;
        const float b0 = bias[col], b1 = bias[col + 1];
#pragma unroll
        for (int mt = 0; mt < 4; mt++) {
            OutT* p0 = C + (size_t)(rowBase + mt * 16) * N + col;
            OutT* p1 = C + (size_t)(rowBase + mt * 16 + 8) * N + col;
            if constexpr (sizeof(OutT) == 4) {
                *reinterpret_cast<float2*>(p0) =
                    make_float2(acc[mt][nt][0] + b0, acc[mt][nt][1] + b1);
                *reinterpret_cast<float2*>(p1) =
                    make_float2(acc[mt][nt][2] + b0, acc[mt][nt][3] + b1);
            } else {
                __half2 h0 = __floats2half2_rn(acc[mt][nt][0] + b0, acc[mt][nt][1] + b1);
                __half2 h1 = __floats2half2_rn(acc[mt][nt][2] + b0, acc[mt][nt][3] + b1);
                *reinterpret_cast<__half2*>(p0) = h0;
                *reinterpret_cast<__half2*>(p1) = h1;
            }
        }
    }
}

// ---------------------------------------------------------------------------
// f32 -> f16 conversion
// ---------------------------------------------------------------------------
__global__ __launch_bounds__(256)
void f2h_kernel(const float4* __restrict__ in, uint2* __restrict__ out, int n4)
{
    for (int i = blockIdx.x * blockDim.x + threadIdx.x; i < n4;
         i += gridDim.x * blockDim.x) {
        float4 v = in[i];
        __half2 h0 = __floats2half2_rn(v.x, v.y);
        __half2 h1 = __floats2half2_rn(v.z, v.w);
        uint2 o;
        o.x = *reinterpret_cast<uint32_t*>(&h0);
        o.y = *reinterpret_cast<uint32_t*>(&h1);
        out[i] = o;
    }
}

// ---------------------------------------------------------------------------
// Head-axis attention per token (faithful "buggy" einsum), fp16 in/out,
// fp32 accumulation, reshape scramble fused into the store.
// ---------------------------------------------------------------------------
__device__ __forceinline__ float dot8h(uint4 a, uint4 b) {
    const __half2* ah = reinterpret_cast<const __half2*>(&a);
    const __half2* bh = reinterpret_cast<const __half2*>(&b);
    float s = 0.0f;
#pragma unroll
    for (int t = 0; t < 4; t++) {
        float2 fa = __half22float2(ah[t]);
        float2 fb = __half22float2(bh[t]);
        s += fa.x * fb.x + fa.y * fb.y;
    }
    return s;
}

__global__ __launch_bounds__(128)
void attn_kernel(const __half* __restrict__ Q,
                 const __half* __restrict__ K,
                 const __half* __restrict__ V,
                 __half* __restrict__ Y)
{
    __shared__ uint4 sQ[4][E_DIM / 8];
    __shared__ uint4 sK[4][E_DIM / 8];
    __shared__ uint4 sV[4][E_DIM / 8];

    const int w    = threadIdx.x >> 5;
    const int lane = threadIdx.x & 31;
    const int token = blockIdx.x * 4 + w;

    const uint4* Q4 = reinterpret_cast<const uint4*>(Q + (size_t)token * E_DIM);
    const uint4* K4 = reinterpret_cast<const uint4*>(K + (size_t)token * E_DIM);
    const uint4* V4 = reinterpret_cast<const uint4*>(V + (size_t)token * E_DIM);

#pragma unroll
    for (int c = 0; c < 4; c++) {
        sQ[w][lane + 32 * c] = Q4[lane + 32 * c];
        sK[w][lane + 32 * c] = K4[lane + 32 * c];
        sV[w][lane + 32 * c] = V4[lane + 32 * c];
    }
    __syncwarp();

    const int i    = lane >> 1;
    const int half = lane & 1;

    uint4 q[8];
#pragma unroll
    for (int c = 0; c < 8; c++) q[c] = sQ[w][i * 8 + c];

    float e[8];
#pragma unroll
    for (int jj = 0; jj < 8; jj++) {
        const int j = half * 8 + jj;
        float dot = 0.0f;
#pragma unroll
        for (int c = 0; c < 8; c++)
            dot += dot8h(q[c], sK[w][j * 8 + c]);
        e[jj] = dot * 0.03125f;   // 1/sqrt(1024)
    }

    float mx = e[0];
#pragma unroll
    for (int jj = 1; jj < 8; jj++) mx = fmaxf(mx, e[jj]);
    mx = fmaxf(mx, __shfl_xor_sync(0xffffffffu, mx, 1));

    float p[8], sum = 0.0f;
#pragma unroll
    for (int jj = 0; jj < 8; jj++) {
        p[jj] = __expf(e[jj] - mx);
        sum += p[jj];
    }
    sum += __shfl_xor_sync(0xffffffffu, sum, 1);
    const float inv = 1.0f / sum;

    float pj[16];
#pragma unroll
    for (int jj = 0; jj < 8; jj++) {
        float mine  = p[jj] * inv;
        float other = __shfl_xor_sync(0xffffffffu, mine, 1);
        pj[half * 8 + jj]       = mine;
        pj[(half ^ 1) * 8 + jj] = other;
    }

    const int n = token / S_LEN;
    const int s = token % S_LEN;
    __half* Yrow = Y + ((size_t)(n * S_LEN + i * 512 + (s >> 4)) * E_DIM)
                     + ((s & 15) * 64) + half * 32;

#pragma unroll
    for (int d8 = 0; d8 < 4; d8++) {
        float acc[8];
#pragma unroll
        for (int t = 0; t < 8; t++) acc[t] = 0.0f;
#pragma unroll
        for (int j = 0; j < 16; j++) {
            uint4 v = sV[w][j * 8 + half * 4 + d8];
            const __half2* vh = reinterpret_cast<const __half2*>(&v);
#pragma unroll
            for (int t = 0; t < 4; t++) {
                float2 fv = __half22float2(vh[t]);
                acc[2 * t]     += pj[j] * fv.x;
                acc[2 * t + 1] += pj[j] * fv.y;
            }
        }
        uint4 o;
        __half2 h0 = __floats2half2_rn(acc[0], acc[1]);
        __half2 h1 = __floats2half2_rn(acc[2], acc[3]);
        __half2 h2 = __floats2half2_rn(acc[4], acc[5]);
        __half2 h3 = __floats2half2_rn(acc[6], acc[7]);
        o.x = *reinterpret_cast<uint32_t*>(&h0);
        o.y = *reinterpret_cast<uint32_t*>(&h1);
        o.z = *reinterpret_cast<uint32_t*>(&h2);
        o.w = *reinterpret_cast<uint32_t*>(&h3);
        *reinterpret_cast<uint4*>(Yrow + d8 * 8) = o;
    }
}

// ---------------------------------------------------------------------------
// Launch
// ---------------------------------------------------------------------------
extern "C" void kernel_launch(void* const* d_in, const int* in_sizes, int n_in,
                              void* d_out, int out_size)
{
    const float* x  = (const float*)d_in[0];
    const float* Ws[4] = { (const float*)d_in[1], (const float*)d_in[2],
                           (const float*)d_in[3], (const float*)d_in[4] };
    const float* bq = (const float*)d_in[5];
    const float* bk = (const float*)d_in[6];
    const float* bv = (const float*)d_in[7];
    const float* bo = (const float*)d_in[8];
    float* out = (float*)d_out;

    __half *Xh, *Wh, *Qh, *Kh, *Vh, *Yh;
    cudaGetSymbolAddress((void**)&Xh, g_Xh);
    cudaGetSymbolAddress((void**)&Wh, g_Wh);
    cudaGetSymbolAddress((void**)&Qh, g_Qh);
    cudaGetSymbolAddress((void**)&Kh, g_Kh);
    cudaGetSymbolAddress((void**)&Vh, g_Vh);
    cudaGetSymbolAddress((void**)&Yh, g_Yh);

    static bool attr_set = false;
    if (!attr_set) {
        cudaFuncSetAttribute(hgemm_bias_kernel<__half>,
                             cudaFuncAttributeMaxDynamicSharedMemorySize, SMEM_BYTES);
        cudaFuncSetAttribute(hgemm_bias_kernel<float>,
                             cudaFuncAttributeMaxDynamicSharedMemorySize, SMEM_BYTES);
        attr_set = true;
    }

    // 1) convert operands to fp16
    const int xn4 = (M_TOT * E_DIM) / 4;
    const int wn4 = (E_DIM * E_DIM) / 4;
    f2h_kernel<<<2048, 256>>>((const float4*)x, (uint2*)Xh, xn4);
    for (int i = 0; i < 4; i++)
        f2h_kernel<<<512, 256>>>((const float4*)Ws[i],
                                 (uint2*)(Wh + (size_t)i * E_DIM * E_DIM), wn4);

    // 2) Q/K/V projections (fp16 outputs)
    dim3 gblock(256);
    dim3 ggrid(E_DIM / BN, M_TOT / BM);
    hgemm_bias_kernel<__half><<<ggrid, gblock, SMEM_BYTES>>>(
        Xh, Wh + 0 * (size_t)E_DIM * E_DIM, bq, Qh, M_TOT, E_DIM, E_DIM);
    hgemm_bias_kernel<__half><<<ggrid, gblock, SMEM_BYTES>>>(
        Xh, Wh + 1 * (size_t)E_DIM * E_DIM, bk, Kh, M_TOT, E_DIM, E_DIM);
    hgemm_bias_kernel<__half><<<ggrid, gblock, SMEM_BYTES>>>(
        Xh, Wh + 2 * (size_t)E_DIM * E_DIM, bv, Vh, M_TOT, E_DIM, E_DIM);

    // 3) head-axis attention + scramble (fp16 in/out)
    attn_kernel<<<M_TOT / 4, 128>>>(Qh, Kh, Vh, Yh);

    // 4) output projection (fp32 out)
    hgemm_bias_kernel<float><<<ggrid, gblock, SMEM_BYTES>>>(
        Yh, Wh + 3 * (size_t)E_DIM * E_DIM, bo, out, M_TOT, E_DIM, E_DIM);
}